// round 8
// baseline (speedup 1.0000x reference)
#include <cuda_runtime.h>
#include <stdint.h>

#define SEQ   4096
#define NPOS  32768
#define SLOT  80
#define ROW_BYTES (SLOT * 4)                 // 320
#define NTAB  16
#define POS_BYTES (NTAB * ROW_BYTES)         // 5120 per position
#define P     2                              // positions per block
#define THREADS (P * NTAB)                   // 32
#define STAGE_BYTES (P * POS_BYTES)          // 10240
#define NBLOCKS (NPOS / P)                   // 16384

// table sizes: 8 x n=2 then 8 x n=3
__constant__ unsigned int c_sizes[16] = {
    6619u, 6637u, 6653u, 6659u, 6661u, 6673u, 6679u, 6689u,
    65521u, 65537u, 65539u, 65543u, 65551u, 65557u, 65563u, 65579u
};

struct Tables { const float* t[16]; };

__device__ __forceinline__ uint32_t smem_u32(const void* p) {
    uint32_t a;
    asm("{ .reg .u64 tmp; cvta.to.shared.u64 tmp, %1; cvt.u32.u64 %0, tmp; }"
        : "=r"(a) : "l"(p));
    return a;
}

__global__ __launch_bounds__(THREADS) void engram_kernel(
    const int* __restrict__ ids,      // [B, S] int32
    const int* __restrict__ seeds,    // [3, 8] int32
    Tables tp,
    float* __restrict__ out)          // [B, S, 1280] fp32
{
    __shared__ __align__(16) unsigned char stage[STAGE_BYTES];
    __shared__ __align__(8)  unsigned long long mbar[P];

    const int tid = threadIdx.x;
    const uint32_t stage_a = smem_u32(stage);
    const uint32_t mbar_a0 = smem_u32(mbar);

    if (tid < P) {
        asm volatile("mbarrier.init.shared.b64 [%0], 1;"
                     :: "r"(mbar_a0 + tid * 8) : "memory");
    }
    __syncwarp();

    const int p    = tid >> 4;           // position within block
    const int tab  = tid & 15;           // table index
    const int head = tab & 7;
    const int pos  = blockIdx.x * P + p;
    const int s    = pos & (SEQ - 1);
    const uint32_t my_mbar = mbar_a0 + p * 8;

    // L2 policies:
    //  - output stores: evict_first (streaming; don't thrash read working set)
    //  - gather loads: evict_last (n3 unique set ~66MB fits L2; ~21% re-hits)
    uint64_t pol_ef, pol_el;
    asm("createpolicy.fractional.L2::evict_first.b64 %0, 1.0;" : "=l"(pol_ef));
    asm("createpolicy.fractional.L2::evict_last.b64 %0, 1.0;"  : "=l"(pol_el));

    // hash
    const unsigned long long id0 = (unsigned int)__ldg(ids + pos);
    const unsigned long long id1 =
        (s >= 1) ? (unsigned long long)(unsigned int)__ldg(ids + pos - 1) : 0ull;

    unsigned long long h;
    if (tab < 8) {
        h = (id1 * (unsigned long long)(unsigned int)__ldg(seeds + head))
          ^ (id0 * (unsigned long long)(unsigned int)__ldg(seeds + 8 + head));
    } else {
        const unsigned long long id2 =
            (s >= 2) ? (unsigned long long)(unsigned int)__ldg(ids + pos - 2) : 0ull;
        h = (id2 * (unsigned long long)(unsigned int)__ldg(seeds + head))
          ^ (id1 * (unsigned long long)(unsigned int)__ldg(seeds + 8 + head))
          ^ (id0 * (unsigned long long)(unsigned int)__ldg(seeds + 16 + head));
    }
    const unsigned int idx = (unsigned int)(h % (unsigned long long)c_sizes[tab]);

    // drain thread posts the expected byte count for this position's barrier
    if (tab == 0) {
        asm volatile("mbarrier.arrive.expect_tx.shared.b64 _, [%0], %1;"
                     :: "r"(my_mbar), "r"((int)POS_BYTES) : "memory");
    }
    // all 16 threads of this position issue their row copy to the position barrier
    {
        const char*    src = (const char*)tp.t[tab] + (size_t)idx * ROW_BYTES;
        const uint32_t dst = stage_a + (uint32_t)tid * ROW_BYTES;  // (p*16+tab)*320
        asm volatile(
            "cp.async.bulk.shared::cta.global.mbarrier::complete_tx::bytes.L2::cache_hint "
            "[%0], [%1], %2, [%3], %4;"
            :: "r"(dst), "l"(src), "r"((int)ROW_BYTES), "r"(my_mbar), "l"(pol_el)
            : "memory");
    }

    // per-position drain: as soon as this position's 5120B are in smem,
    // issue one contiguous 5KB bulk store. P independent drain threads.
    if (tab == 0) {
        asm volatile(
            "{\n\t"
            ".reg .pred P1;\n\t"
            "W_%=:\n\t"
            "mbarrier.try_wait.parity.shared.b64 P1, [%0], 0, 0x989680;\n\t"
            "@P1 bra.uni D_%=;\n\t"
            "bra.uni W_%=;\n\t"
            "D_%=:\n\t"
            "}"
            :: "r"(my_mbar) : "memory");

        char* gdst = (char*)out + (size_t)pos * POS_BYTES;
        asm volatile(
            "cp.async.bulk.global.shared::cta.bulk_group.L2::cache_hint "
            "[%0], [%1], %2, %3;"
            :: "l"(gdst), "r"(stage_a + (uint32_t)p * POS_BYTES), "r"((int)POS_BYTES),
               "l"(pol_ef)
            : "memory");
        asm volatile("cp.async.bulk.commit_group;" ::: "memory");
        // only wait until the store has READ smem (CTA slot may then recycle);
        // global write completion is guaranteed by kernel-end semantics.
        asm volatile("cp.async.bulk.wait_group.read 0;" ::: "memory");
    }
}

extern "C" void kernel_launch(void* const* d_in, const int* in_sizes, int n_in,
                              void* d_out, int out_size)
{
    const int* ids   = (const int*)d_in[0];
    const int* seeds = (const int*)d_in[1];

    Tables tp;
    #pragma unroll
    for (int i = 0; i < 16; i++) tp.t[i] = (const float*)d_in[2 + i];

    engram_kernel<<<NBLOCKS, THREADS>>>(ids, seeds, tp, (float*)d_out);
}